// round 13
// baseline (speedup 1.0000x reference)
#include <cuda_runtime.h>
#include <cstdint>

#define Nn   3072
#define FIN  512
#define NH   8
#define CC   512
#define NC   16
#define LRA  0.2f
#define JSPLIT 3
#define JCHUNK 1024
#define TI   64
#define TJ   32
#define NT3  32      // JCHUNK/TJ
#define KSP  516     // p_s per-j stride in floats (129 float4s -> conflict-free)
#define HS   64
#define WB   16384   // wh_s buffer stride (floats)
#define TI5  8

typedef unsigned long long u64;
typedef uint32_t u32;

// ---- static device scratch ----
__device__ float g_Wh[Nn * CC];
__device__ float g_srcT[Nn * NH], g_dstT[Nn * NH], g_Zinv[Nn * NH];
__device__ float g_hp[JSPLIT][Nn * CC];
__device__ float g_Wh2[Nn * NC];
__device__ float g_s2[Nn], g_d2[Nn];

__device__ __forceinline__ float lrelu(float x) { return fmaxf(x, LRA * x); }
__device__ __forceinline__ void ffma2(u64& d, u64 a, u64 b) {
    asm("fma.rn.f32x2 %0, %1, %2, %0;" : "+l"(d) : "l"(a), "l"(b));
}
__device__ __forceinline__ float2 unpk(u64 v) {
    float2 r;
    asm("mov.b64 {%0, %1}, %2;" : "=f"(r.x), "=f"(r.y) : "l"(v));
    return r;
}
__device__ __forceinline__ void cp16(u32 s, const void* g) {
    asm volatile("cp.async.cg.shared.global [%0], [%1], 16;" :: "r"(s), "l"(g));
}
__device__ __forceinline__ void cp_commit() {
    asm volatile("cp.async.commit_group;" ::: "memory");
}
__device__ __forceinline__ void cp_waitall() {
    asm volatile("cp.async.wait_group 0;" ::: "memory");
}

// ================= K1: Wh = x @ W (64x64 tile SGEMM, f32x2, pipelined) =====
__global__ void __launch_bounds__(256) k1_gemm(const float* __restrict__ x,
                                               const float* __restrict__ W) {
    __shared__ float As[16][64], Bs[16][64];
    int t = threadIdx.x, tx = t & 15, ty = t >> 4;
    int row0 = blockIdx.y * 64, col0 = blockIdx.x * 64;
    const float* Wb = W + (size_t)(col0 >> 6) * FIN * 64;
    int ra_r = t >> 2, ra_c = (t & 3) << 2, rb_r = t >> 4, rb_c = (t & 15) << 2;
    float4 ra = *(const float4*)&x[(size_t)(row0 + ra_r) * FIN + ra_c];
    float4 rb = *(const float4*)&Wb[(size_t)rb_r * 64 + rb_c];
    u64 acc[2][4];
#pragma unroll
    for (int i = 0; i < 2; i++)
#pragma unroll
        for (int j = 0; j < 4; j++) acc[i][j] = 0ull;
    for (int k0 = 0; k0 < FIN; k0 += 16) {
        As[ra_c][ra_r] = ra.x; As[ra_c + 1][ra_r] = ra.y;
        As[ra_c + 2][ra_r] = ra.z; As[ra_c + 3][ra_r] = ra.w;
        *(float4*)&Bs[rb_r][rb_c] = rb;
        __syncthreads();
        if (k0 + 16 < FIN) {
            ra = *(const float4*)&x[(size_t)(row0 + ra_r) * FIN + k0 + 16 + ra_c];
            rb = *(const float4*)&Wb[(size_t)(k0 + 16 + rb_r) * 64 + rb_c];
        }
#pragma unroll
        for (int k = 0; k < 16; k++) {
            ulonglong2 ap = *(const ulonglong2*)&As[k][ty * 4];
            float4 b4 = *(const float4*)&Bs[k][tx * 4];
            u64 bd[4];
            asm("mov.b64 %0, {%1, %1};" : "=l"(bd[0]) : "f"(b4.x));
            asm("mov.b64 %0, {%1, %1};" : "=l"(bd[1]) : "f"(b4.y));
            asm("mov.b64 %0, {%1, %1};" : "=l"(bd[2]) : "f"(b4.z));
            asm("mov.b64 %0, {%1, %1};" : "=l"(bd[3]) : "f"(b4.w));
#pragma unroll
            for (int c = 0; c < 4; c++) {
                ffma2(acc[0][c], ap.x, bd[c]);
                ffma2(acc[1][c], ap.y, bd[c]);
            }
        }
        __syncthreads();
    }
#pragma unroll
    for (int rp = 0; rp < 2; rp++) {
        float2 c0 = unpk(acc[rp][0]), c1 = unpk(acc[rp][1]);
        float2 c2 = unpk(acc[rp][2]), c3 = unpk(acc[rp][3]);
        int r = row0 + ty * 4 + rp * 2;
        *(float4*)&g_Wh[(size_t)r * CC + col0 + tx * 4] =
            make_float4(c0.x, c1.x, c2.x, c3.x);
        *(float4*)&g_Wh[(size_t)(r + 1) * CC + col0 + tx * 4] =
            make_float4(c0.y, c1.y, c2.y, c3.y);
    }
}

// ================= K1b: src/dst projections =================
__global__ void __launch_bounds__(256) k_srcdst(const float* __restrict__ a_src,
                                                const float* __restrict__ a_dst) {
    int n = blockIdx.x, h = threadIdx.x >> 5, lane = threadIdx.x & 31;
    const float* wh = g_Wh + (size_t)n * CC + h * 64;
    float w0 = wh[lane], w1 = wh[lane + 32];
    float s = w0 * a_src[h * 64 + lane] + w1 * a_src[h * 64 + lane + 32];
    float d = w0 * a_dst[h * 64 + lane] + w1 * a_dst[h * 64 + lane + 32];
#pragma unroll
    for (int o = 16; o; o >>= 1) {
        s += __shfl_down_sync(0xffffffffu, s, o);
        d += __shfl_down_sync(0xffffffffu, d, o);
    }
    if (!lane) { g_srcT[n * NH + h] = s; g_dstT[n * NH + h] = d; }
}

// ========= K2: softmax denominators Z[h,i], batched unconditional loads ====
__global__ void __launch_bounds__(256) k2_z(const int* __restrict__ adj) {
    int i = blockIdx.x;
    float sr[NH], sum[NH];
#pragma unroll
    for (int h = 0; h < NH; h++) { sr[h] = g_srcT[i * NH + h]; sum[h] = 0.f; }
    const int* arow = adj + (size_t)i * Nn;
    int t4 = threadIdx.x * 4;
#pragma unroll
    for (int it = 0; it < 3; it++) {
        int j = it * 1024 + t4;
        int4 a = *(const int4*)&arow[j];
        float4 d0[4], d1[4];
#pragma unroll
        for (int q = 0; q < 4; q++) {
            const float4* dp = (const float4*)(g_dstT + (size_t)(j + q) * NH);
            d0[q] = dp[0];
            d1[q] = dp[1];
        }
        int am[4] = {a.x, a.y, a.z, a.w};
#pragma unroll
        for (int q = 0; q < 4; q++) {
            if (am[q] > 0) {
                float dv[8] = {d0[q].x, d0[q].y, d0[q].z, d0[q].w,
                               d1[q].x, d1[q].y, d1[q].z, d1[q].w};
#pragma unroll
                for (int h = 0; h < NH; h++)
                    sum[h] += __expf(lrelu(sr[h] + dv[h]));
            }
        }
    }
    __shared__ float red[8][NH];
    int lane = threadIdx.x & 31, w = threadIdx.x >> 5;
#pragma unroll
    for (int h = 0; h < NH; h++) {
        float v = sum[h];
#pragma unroll
        for (int o = 16; o; o >>= 1) v += __shfl_down_sync(0xffffffffu, v, o);
        if (!lane) red[w][h] = v;
    }
    __syncthreads();
    if (threadIdx.x < NH) {
        float v = 0.f;
#pragma unroll
        for (int ww = 0; ww < 8; ww++) v += red[ww][threadIdx.x];
        g_Zinv[i * NH + threadIdx.x] = 1.f / v;
    }
}

// ====== K3: fused pgen + avg write + FFMA2 (att @ Wh), full cp.async ======
// (round-10 form, unchanged — measured 209 us)
__global__ void __launch_bounds__(512) k3_att(const int* __restrict__ adj,
                                              float* __restrict__ avg) {
    extern __shared__ float sm[];
    float* wh_s   = sm;
    float* p_s    = sm + 32768;
    float* src_s  = sm + 49280;
    float* zinv_s = sm + 49792;
    float* dst_b  = sm + 50304;
    int*   adj_b  = (int*)(sm + 50816);

    int t = threadIdx.x;
    int i0 = blockIdx.y * TI;
    int jbase = blockIdx.x * JCHUNK;

    src_s[(t & 7) * TI + (t >> 3)]  = g_srcT[i0 * NH + t];
    zinv_s[(t & 7) * TI + (t >> 3)] = g_Zinv[i0 * NH + t];

    int tc = t & 127, tr = t >> 7;
    int lane = t & 31, w = t >> 5;
    int r0p = w * 4;
    int r0g = tr * 16;
    int hg = tc >> 4;
    int col0 = tc * 4;

    u32 whs_u  = (u32)__cvta_generic_to_shared(wh_s);
    u32 adjb_u = (u32)__cvta_generic_to_shared(adj_b);
    u32 dstb_u = (u32)__cvta_generic_to_shared(dst_b);
    int cp_row = t >> 3, cp_seg = (t & 7) << 2;

    auto issue_tile = [&](int tile, int buf) {
        int j0t = jbase + tile * TJ;
        cp16(adjb_u + (u32)(buf * 8192 + ((cp_row << 5) + cp_seg) * 4),
             adj + (size_t)(i0 + cp_row) * Nn + j0t + cp_seg);
        if (t < 64)
            cp16(dstb_u + (u32)(buf * 1024 + t * 16),
                 (const char*)g_dstT + ((size_t)j0t * NH + t * 4) * 4);
#pragma unroll
        for (int q = 0; q < 8; q++) {
            int idx = q * 512 + t;
            int jj = idx >> 7, c4 = (idx & 127) << 2;
            cp16(whs_u + (u32)((buf * WB + jj * CC + c4) * 4),
                 &g_Wh[(size_t)(j0t + jj) * CC + c4]);
        }
    };

    issue_tile(0, 0);
    cp_commit();
    cp_waitall();

    u64 acc[8][4];
#pragma unroll
    for (int a = 0; a < 8; a++)
#pragma unroll
        for (int c = 0; c < 4; c++) acc[a][c] = 0ull;
    __syncthreads();

    for (int jt = 0; jt < NT3; jt++) {
        int b = jt & 1;
        int j0 = jbase + jt * TJ;
        if (jt + 1 < NT3) {
            issue_tile(jt + 1, 1 - b);
            cp_commit();
        }
        {
            const float* db = dst_b + b * 256;
            const int*   ab = adj_b + b * 2048;
            float4 dva = *(const float4*)&db[lane * 8];
            float4 dvb = *(const float4*)&db[lane * 8 + 4];
            float dv[8] = {dva.x, dva.y, dva.z, dva.w, dvb.x, dvb.y, dvb.z, dvb.w};
            float msk[4], sumv[4];
#pragma unroll
            for (int rr = 0; rr < 4; rr++) {
                msk[rr] = ab[(r0p + rr) * 32 + lane] > 0 ? 1.f : 0.f;
                sumv[rr] = 0.f;
            }
#pragma unroll
            for (int m = 0; m < 4; m++) {
                int h0 = 2 * m;
                float4 s0 = *(const float4*)&src_s[h0 * TI + r0p];
                float4 s1 = *(const float4*)&src_s[(h0 + 1) * TI + r0p];
                float4 z0 = *(const float4*)&zinv_s[h0 * TI + r0p];
                float4 z1 = *(const float4*)&zinv_s[(h0 + 1) * TI + r0p];
                float4 v0, v1;
                v0.x = __expf(lrelu(s0.x + dv[h0])) * z0.x * msk[0];
                v0.y = __expf(lrelu(s0.y + dv[h0])) * z0.y * msk[1];
                v0.z = __expf(lrelu(s0.z + dv[h0])) * z0.z * msk[2];
                v0.w = __expf(lrelu(s0.w + dv[h0])) * z0.w * msk[3];
                v1.x = __expf(lrelu(s1.x + dv[h0 + 1])) * z1.x * msk[0];
                v1.y = __expf(lrelu(s1.y + dv[h0 + 1])) * z1.y * msk[1];
                v1.z = __expf(lrelu(s1.z + dv[h0 + 1])) * z1.z * msk[2];
                v1.w = __expf(lrelu(s1.w + dv[h0 + 1])) * z1.w * msk[3];
                sumv[0] += v0.x + v1.x; sumv[1] += v0.y + v1.y;
                sumv[2] += v0.z + v1.z; sumv[3] += v0.w + v1.w;
                *(float4*)&p_s[lane * KSP + h0 * HS + r0p] = v0;
                *(float4*)&p_s[lane * KSP + (h0 + 1) * HS + r0p] = v1;
            }
#pragma unroll
            for (int rr = 0; rr < 4; rr++)
                avg[(size_t)(i0 + r0p + rr) * Nn + j0 + lane] = sumv[rr] * 0.125f;
        }
        __syncthreads();
        const float* whb = wh_s + b * WB;
#pragma unroll 4
        for (int k = 0; k < TJ; k++) {
            const float* pb = &p_s[k * KSP + hg * HS + r0g];
            ulonglong2 a01 = *(const ulonglong2*)(pb);
            ulonglong2 a23 = *(const ulonglong2*)(pb + 4);
            ulonglong2 a45 = *(const ulonglong2*)(pb + 8);
            ulonglong2 a67 = *(const ulonglong2*)(pb + 12);
            float4 b4 = *(const float4*)&whb[k * CC + col0];
            u64 bd[4];
            asm("mov.b64 %0, {%1, %1};" : "=l"(bd[0]) : "f"(b4.x));
            asm("mov.b64 %0, {%1, %1};" : "=l"(bd[1]) : "f"(b4.y));
            asm("mov.b64 %0, {%1, %1};" : "=l"(bd[2]) : "f"(b4.z));
            asm("mov.b64 %0, {%1, %1};" : "=l"(bd[3]) : "f"(b4.w));
#pragma unroll
            for (int c = 0; c < 4; c++) {
                ffma2(acc[0][c], a01.x, bd[c]);
                ffma2(acc[1][c], a01.y, bd[c]);
                ffma2(acc[2][c], a23.x, bd[c]);
                ffma2(acc[3][c], a23.y, bd[c]);
                ffma2(acc[4][c], a45.x, bd[c]);
                ffma2(acc[5][c], a45.y, bd[c]);
                ffma2(acc[6][c], a67.x, bd[c]);
                ffma2(acc[7][c], a67.y, bd[c]);
            }
        }
        cp_waitall();
        __syncthreads();
    }
    float* dst = g_hp[blockIdx.x];
#pragma unroll
    for (int rp = 0; rp < 8; rp++) {
        float2 c0 = unpk(acc[rp][0]), c1 = unpk(acc[rp][1]);
        float2 c2 = unpk(acc[rp][2]), c3 = unpk(acc[rp][3]);
        int r = i0 + r0g + rp * 2;
        *(float4*)&dst[(size_t)r * CC + col0] = make_float4(c0.x, c1.x, c2.x, c3.x);
        *(float4*)&dst[(size_t)(r + 1) * CC + col0] = make_float4(c0.y, c1.y, c2.y, c3.y);
    }
}

// ====== K4: elu + Wh2 = x2 @ W_out + src2/dst2 (round-10 form) ======
__global__ void __launch_bounds__(128) k4_out(const float* __restrict__ Wout,
                                              const float* __restrict__ aos,
                                              const float* __restrict__ aod) {
    int w = threadIdx.x >> 5, lane = threadIdx.x & 31;
    int row = blockIdx.x * 4 + w;
    const float* h0 = g_hp[0] + (size_t)row * CC;
    const float* h1 = g_hp[1] + (size_t)row * CC;
    const float* h2 = g_hp[2] + (size_t)row * CC;
    float acc[NC];
#pragma unroll
    for (int c = 0; c < NC; c++) acc[c] = 0.f;
#pragma unroll 4
    for (int m = 0; m < FIN / 32; m++) {
        int k = m * 32 + lane;
        float v = h0[k] + h1[k] + h2[k];
        v = v > 0.f ? v : (__expf(v) - 1.f);   // elu
        const float4* wp = (const float4*)(Wout + (size_t)k * NC);
        float4 w0 = wp[0], w1 = wp[1], w2 = wp[2], w3 = wp[3];
        acc[0] += v * w0.x; acc[1] += v * w0.y; acc[2] += v * w0.z; acc[3] += v * w0.w;
        acc[4] += v * w1.x; acc[5] += v * w1.y; acc[6] += v * w1.z; acc[7] += v * w1.w;
        acc[8] += v * w2.x; acc[9] += v * w2.y; acc[10] += v * w2.z; acc[11] += v * w2.w;
        acc[12] += v * w3.x; acc[13] += v * w3.y; acc[14] += v * w3.z; acc[15] += v * w3.w;
    }
#pragma unroll
    for (int c = 0; c < NC; c++) {
        float v = acc[c];
#pragma unroll
        for (int o = 16; o; o >>= 1) v += __shfl_down_sync(0xffffffffu, v, o);
        acc[c] = v;
    }
    if (!lane) {
        float s = 0.f, d = 0.f;
#pragma unroll
        for (int c = 0; c < NC; c++) {
            g_Wh2[(size_t)row * NC + c] = acc[c];
            s += acc[c] * aos[c];
            d += acc[c] * aod[c];
        }
        g_s2[row] = s;
        g_d2[row] = d;
    }
}

// ====== K5: output attention + log_softmax (round-10 form) ======
__global__ void __launch_bounds__(256) k5_final(const int* __restrict__ adj,
                                                float* __restrict__ out) {
    extern __shared__ float sm5[];
    float* p   = sm5;                 // TI5*Nn
    float* w2s = p + TI5 * Nn;        // 256*17
    float* red = w2s + 256 * 17;      // 64
    int i0 = blockIdx.x * TI5;
    int t = threadIdx.x, lane = t & 31, w = t >> 5;

    float zs[TI5], s2v[TI5];
#pragma unroll
    for (int i = 0; i < TI5; i++) { zs[i] = 0.f; s2v[i] = g_s2[i0 + i]; }
    for (int j = t; j < Nn; j += 256) {
        float dv = g_d2[j];
#pragma unroll
        for (int i = 0; i < TI5; i++) {
            float pv = 0.f;
            if (adj[(size_t)(i0 + i) * Nn + j] > 0)
                pv = __expf(lrelu(s2v[i] + dv));
            p[i * Nn + j] = pv;
            zs[i] += pv;
        }
    }
#pragma unroll
    for (int i = 0; i < TI5; i++) {
        float v = zs[i];
#pragma unroll
        for (int o = 16; o; o >>= 1) v += __shfl_down_sync(0xffffffffu, v, o);
        if (!lane) red[w * TI5 + i] = v;
    }
    __syncthreads();
    float Z = 0.f;
#pragma unroll
    for (int ww = 0; ww < 8; ww++) Z += red[ww * TI5 + w];
    float zinv = 1.f / Z;

    float acc[NC];
#pragma unroll
    for (int c = 0; c < NC; c++) acc[c] = 0.f;
    for (int j0 = 0; j0 < Nn; j0 += 256) {
        __syncthreads();
        {
            const float4* gw = (const float4*)&g_Wh2[(size_t)(j0 + t) * NC];
            float4 v0 = gw[0], v1 = gw[1], v2 = gw[2], v3 = gw[3];
            float* ds = &w2s[t * 17];
            ds[0] = v0.x; ds[1] = v0.y; ds[2] = v0.z; ds[3] = v0.w;
            ds[4] = v1.x; ds[5] = v1.y; ds[6] = v1.z; ds[7] = v1.w;
            ds[8] = v2.x; ds[9] = v2.y; ds[10] = v2.z; ds[11] = v2.w;
            ds[12] = v3.x; ds[13] = v3.y; ds[14] = v3.z; ds[15] = v3.w;
        }
        __syncthreads();
#pragma unroll
        for (int jj0 = 0; jj0 < 256; jj0 += 32) {
            int jj = jj0 + lane;
            float pv = p[w * Nn + j0 + jj];
            const float* wr = &w2s[jj * 17];
#pragma unroll
            for (int c = 0; c < NC; c++) acc[c] += pv * wr[c];
        }
    }
#pragma unroll
    for (int c = 0; c < NC; c++) {
        float v = acc[c];
#pragma unroll
        for (int o = 16; o; o >>= 1) v += __shfl_down_sync(0xffffffffu, v, o);
        acc[c] = v;
    }
    if (!lane) {
        float ho[NC];
        float mx = -1e30f;
#pragma unroll
        for (int c = 0; c < NC; c++) { ho[c] = acc[c] * zinv; mx = fmaxf(mx, ho[c]); }
        float se = 0.f;
#pragma unroll
        for (int c = 0; c < NC; c++) se += __expf(ho[c] - mx);
        float lse = mx + __logf(se);
#pragma unroll
        for (int c = 0; c < NC; c++) out[(size_t)(i0 + w) * NC + c] = ho[c] - lse;
    }
}

// =======================================================================
extern "C" void kernel_launch(void* const* d_in, const int* in_sizes, int n_in,
                              void* d_out, int out_size) {
    const float* x = (const float*)d_in[0];
    const int* adj = (const int*)d_in[1];
    const float* Whd = (const float*)d_in[2];
    const float* a_src = (const float*)d_in[3];
    const float* a_dst = (const float*)d_in[4];
    const float* Wout = (const float*)d_in[5];
    const float* aos = (const float*)d_in[6];
    const float* aod = (const float*)d_in[7];
    float* out = (float*)d_out;
    float* avg = out + (size_t)Nn * NC;

    const int SMEM3 = 54912 * 4;   // 219,648 B
    const int SMEM5 = (TI5 * Nn + 256 * 17 + 64) * 4;
    cudaFuncSetAttribute(k3_att, cudaFuncAttributeMaxDynamicSharedMemorySize, SMEM3);
    cudaFuncSetAttribute(k5_final, cudaFuncAttributeMaxDynamicSharedMemorySize, SMEM5);

    k1_gemm<<<dim3(CC / 64, Nn / 64), 256>>>(x, Whd);
    k_srcdst<<<Nn, 256>>>(a_src, a_dst);
    k2_z<<<Nn, 256>>>(adj);
    k3_att<<<dim3(JSPLIT, Nn / TI), 512, SMEM3>>>(adj, avg);
    k4_out<<<Nn / 4, 128>>>(Wout, aos, aod);
    k5_final<<<Nn / TI5, 256, SMEM5>>>(adj, out);
}

// round 14
// speedup vs baseline: 1.1324x; 1.1324x over previous
#include <cuda_runtime.h>
#include <cstdint>

#define Nn   3072
#define FIN  512
#define NH   8
#define CC   512
#define NC   16
#define LRA  0.2f
#define JSPLIT 3
#define JCHUNK 1024
#define TI   64
#define TJ   32
#define NT3  32      // JCHUNK/TJ
#define KSP  516     // p_s per-j stride in floats (129 float4s -> conflict-free)
#define HS   64
#define WB   16384   // wh_s buffer stride (floats)
#define TI5  8

typedef unsigned long long u64;
typedef uint32_t u32;

// ---- static device scratch ----
__device__ float g_Wh[Nn * CC];
__device__ float g_srcT[Nn * NH], g_dstT[Nn * NH], g_Zinv[Nn * NH];
__device__ float g_hp[JSPLIT][Nn * CC];
__device__ float g_Wh2[Nn * NC];
__device__ float g_s2[Nn], g_d2[Nn];

__device__ __forceinline__ float lrelu(float x) { return fmaxf(x, LRA * x); }
__device__ __forceinline__ void ffma2(u64& d, u64 a, u64 b) {
    asm("fma.rn.f32x2 %0, %1, %2, %0;" : "+l"(d) : "l"(a), "l"(b));
}
__device__ __forceinline__ float2 unpk(u64 v) {
    float2 r;
    asm("mov.b64 {%0, %1}, %2;" : "=f"(r.x), "=f"(r.y) : "l"(v));
    return r;
}
__device__ __forceinline__ void cp16(u32 s, const void* g) {
    asm volatile("cp.async.cg.shared.global [%0], [%1], 16;" :: "r"(s), "l"(g));
}
__device__ __forceinline__ void cp_commit() {
    asm volatile("cp.async.commit_group;" ::: "memory");
}
__device__ __forceinline__ void cp_waitall() {
    asm volatile("cp.async.wait_group 0;" ::: "memory");
}

// ====== K1: Wh = x @ W (f32x2, pipelined) + fused src/dst projections ======
__global__ void __launch_bounds__(256) k1_gemm(const float* __restrict__ x,
                                               const float* __restrict__ W,
                                               const float* __restrict__ a_src,
                                               const float* __restrict__ a_dst) {
    __shared__ float As[16][64], Bs[16][64];
    int t = threadIdx.x, tx = t & 15, ty = t >> 4;
    int row0 = blockIdx.y * 64, col0 = blockIdx.x * 64;
    int h = col0 >> 6;
    const float* Wb = W + (size_t)h * FIN * 64;
    int ra_r = t >> 2, ra_c = (t & 3) << 2, rb_r = t >> 4, rb_c = (t & 15) << 2;
    float4 ra = *(const float4*)&x[(size_t)(row0 + ra_r) * FIN + ra_c];
    float4 rb = *(const float4*)&Wb[(size_t)rb_r * 64 + rb_c];
    u64 acc[2][4];
#pragma unroll
    for (int i = 0; i < 2; i++)
#pragma unroll
        for (int j = 0; j < 4; j++) acc[i][j] = 0ull;
    for (int k0 = 0; k0 < FIN; k0 += 16) {
        As[ra_c][ra_r] = ra.x; As[ra_c + 1][ra_r] = ra.y;
        As[ra_c + 2][ra_r] = ra.z; As[ra_c + 3][ra_r] = ra.w;
        *(float4*)&Bs[rb_r][rb_c] = rb;
        __syncthreads();
        if (k0 + 16 < FIN) {
            ra = *(const float4*)&x[(size_t)(row0 + ra_r) * FIN + k0 + 16 + ra_c];
            rb = *(const float4*)&Wb[(size_t)(k0 + 16 + rb_r) * 64 + rb_c];
        }
#pragma unroll
        for (int k = 0; k < 16; k++) {
            ulonglong2 ap = *(const ulonglong2*)&As[k][ty * 4];
            float4 b4 = *(const float4*)&Bs[k][tx * 4];
            u64 bd[4];
            asm("mov.b64 %0, {%1, %1};" : "=l"(bd[0]) : "f"(b4.x));
            asm("mov.b64 %0, {%1, %1};" : "=l"(bd[1]) : "f"(b4.y));
            asm("mov.b64 %0, {%1, %1};" : "=l"(bd[2]) : "f"(b4.z));
            asm("mov.b64 %0, {%1, %1};" : "=l"(bd[3]) : "f"(b4.w));
#pragma unroll
            for (int c = 0; c < 4; c++) {
                ffma2(acc[0][c], ap.x, bd[c]);
                ffma2(acc[1][c], ap.y, bd[c]);
            }
        }
        __syncthreads();
    }
    float4 as4 = *(const float4*)&a_src[col0 + tx * 4];
    float4 ad4 = *(const float4*)&a_dst[col0 + tx * 4];
    float sr_[4], dr_[4];
#pragma unroll
    for (int rp = 0; rp < 2; rp++) {
        float2 cv[4];
#pragma unroll
        for (int c = 0; c < 4; c++) cv[c] = unpk(acc[rp][c]);
        int r = row0 + ty * 4 + rp * 2;
        *(float4*)&g_Wh[(size_t)r * CC + col0 + tx * 4] =
            make_float4(cv[0].x, cv[1].x, cv[2].x, cv[3].x);
        *(float4*)&g_Wh[(size_t)(r + 1) * CC + col0 + tx * 4] =
            make_float4(cv[0].y, cv[1].y, cv[2].y, cv[3].y);
        sr_[rp * 2]     = cv[0].x * as4.x + cv[1].x * as4.y + cv[2].x * as4.z + cv[3].x * as4.w;
        sr_[rp * 2 + 1] = cv[0].y * as4.x + cv[1].y * as4.y + cv[2].y * as4.z + cv[3].y * as4.w;
        dr_[rp * 2]     = cv[0].x * ad4.x + cv[1].x * ad4.y + cv[2].x * ad4.z + cv[3].x * ad4.w;
        dr_[rp * 2 + 1] = cv[0].y * ad4.x + cv[1].y * ad4.y + cv[2].y * ad4.z + cv[3].y * ad4.w;
    }
#pragma unroll
    for (int rr = 0; rr < 4; rr++) {
        float s = sr_[rr], d = dr_[rr];
#pragma unroll
        for (int o = 8; o; o >>= 1) {
            s += __shfl_down_sync(0xffffffffu, s, o, 16);
            d += __shfl_down_sync(0xffffffffu, d, o, 16);
        }
        if (tx == 0) {
            int r = row0 + ty * 4 + rr;
            g_srcT[r * NH + h] = s;
            g_dstT[r * NH + h] = d;
        }
    }
}

// ================= K2: softmax denominators Z[h,i] (round-10 form) =========
__global__ void __launch_bounds__(256) k2_z(const int* __restrict__ adj) {
    int i = blockIdx.x;
    float sr[NH], sum[NH];
#pragma unroll
    for (int h = 0; h < NH; h++) { sr[h] = g_srcT[i * NH + h]; sum[h] = 0.f; }
    const int* arow = adj + (size_t)i * Nn;
    for (int j = threadIdx.x; j < Nn; j += 256) {
        if (arow[j] > 0) {
            const float4* dp = (const float4*)(g_dstT + (size_t)j * NH);
            float4 d0 = dp[0], d1 = dp[1];
            float dv[8] = {d0.x, d0.y, d0.z, d0.w, d1.x, d1.y, d1.z, d1.w};
#pragma unroll
            for (int h = 0; h < NH; h++) sum[h] += __expf(lrelu(sr[h] + dv[h]));
        }
    }
    __shared__ float red[8][NH];
    int lane = threadIdx.x & 31, w = threadIdx.x >> 5;
#pragma unroll
    for (int h = 0; h < NH; h++) {
        float v = sum[h];
#pragma unroll
        for (int o = 16; o; o >>= 1) v += __shfl_down_sync(0xffffffffu, v, o);
        if (!lane) red[w][h] = v;
    }
    __syncthreads();
    if (threadIdx.x < NH) {
        float v = 0.f;
#pragma unroll
        for (int ww = 0; ww < 8; ww++) v += red[ww][threadIdx.x];
        g_Zinv[i * NH + threadIdx.x] = 1.f / v;
    }
}

// ====== K3: fused pgen + avg write + FFMA2 (att @ Wh) — round-10 form ======
__global__ void __launch_bounds__(512) k3_att(const int* __restrict__ adj,
                                              float* __restrict__ avg) {
    extern __shared__ float sm[];
    float* wh_s   = sm;
    float* p_s    = sm + 32768;
    float* src_s  = sm + 49280;
    float* zinv_s = sm + 49792;
    float* dst_b  = sm + 50304;
    int*   adj_b  = (int*)(sm + 50816);

    int t = threadIdx.x;
    int i0 = blockIdx.y * TI;
    int jbase = blockIdx.x * JCHUNK;

    src_s[(t & 7) * TI + (t >> 3)]  = g_srcT[i0 * NH + t];
    zinv_s[(t & 7) * TI + (t >> 3)] = g_Zinv[i0 * NH + t];

    int tc = t & 127, tr = t >> 7;
    int lane = t & 31, w = t >> 5;
    int r0p = w * 4;
    int r0g = tr * 16;
    int hg = tc >> 4;
    int col0 = tc * 4;

    u32 whs_u  = (u32)__cvta_generic_to_shared(wh_s);
    u32 adjb_u = (u32)__cvta_generic_to_shared(adj_b);
    u32 dstb_u = (u32)__cvta_generic_to_shared(dst_b);
    int cp_row = t >> 3, cp_seg = (t & 7) << 2;

    auto issue_tile = [&](int tile, int buf) {
        int j0t = jbase + tile * TJ;
        cp16(adjb_u + (u32)(buf * 8192 + ((cp_row << 5) + cp_seg) * 4),
             adj + (size_t)(i0 + cp_row) * Nn + j0t + cp_seg);
        if (t < 64)
            cp16(dstb_u + (u32)(buf * 1024 + t * 16),
                 (const char*)g_dstT + ((size_t)j0t * NH + t * 4) * 4);
#pragma unroll
        for (int q = 0; q < 8; q++) {
            int idx = q * 512 + t;
            int jj = idx >> 7, c4 = (idx & 127) << 2;
            cp16(whs_u + (u32)((buf * WB + jj * CC + c4) * 4),
                 &g_Wh[(size_t)(j0t + jj) * CC + c4]);
        }
    };

    issue_tile(0, 0);
    cp_commit();
    cp_waitall();

    u64 acc[8][4];
#pragma unroll
    for (int a = 0; a < 8; a++)
#pragma unroll
        for (int c = 0; c < 4; c++) acc[a][c] = 0ull;
    __syncthreads();

    for (int jt = 0; jt < NT3; jt++) {
        int b = jt & 1;
        int j0 = jbase + jt * TJ;
        if (jt + 1 < NT3) {
            issue_tile(jt + 1, 1 - b);
            cp_commit();
        }
        {
            const float* db = dst_b + b * 256;
            const int*   ab = adj_b + b * 2048;
            float4 dva = *(const float4*)&db[lane * 8];
            float4 dvb = *(const float4*)&db[lane * 8 + 4];
            float dv[8] = {dva.x, dva.y, dva.z, dva.w, dvb.x, dvb.y, dvb.z, dvb.w};
            float msk[4], sumv[4];
#pragma unroll
            for (int rr = 0; rr < 4; rr++) {
                msk[rr] = ab[(r0p + rr) * 32 + lane] > 0 ? 1.f : 0.f;
                sumv[rr] = 0.f;
            }
#pragma unroll
            for (int m = 0; m < 4; m++) {
                int h0 = 2 * m;
                float4 s0 = *(const float4*)&src_s[h0 * TI + r0p];
                float4 s1 = *(const float4*)&src_s[(h0 + 1) * TI + r0p];
                float4 z0 = *(const float4*)&zinv_s[h0 * TI + r0p];
                float4 z1 = *(const float4*)&zinv_s[(h0 + 1) * TI + r0p];
                float4 v0, v1;
                v0.x = __expf(lrelu(s0.x + dv[h0])) * z0.x * msk[0];
                v0.y = __expf(lrelu(s0.y + dv[h0])) * z0.y * msk[1];
                v0.z = __expf(lrelu(s0.z + dv[h0])) * z0.z * msk[2];
                v0.w = __expf(lrelu(s0.w + dv[h0])) * z0.w * msk[3];
                v1.x = __expf(lrelu(s1.x + dv[h0 + 1])) * z1.x * msk[0];
                v1.y = __expf(lrelu(s1.y + dv[h0 + 1])) * z1.y * msk[1];
                v1.z = __expf(lrelu(s1.z + dv[h0 + 1])) * z1.z * msk[2];
                v1.w = __expf(lrelu(s1.w + dv[h0 + 1])) * z1.w * msk[3];
                sumv[0] += v0.x + v1.x; sumv[1] += v0.y + v1.y;
                sumv[2] += v0.z + v1.z; sumv[3] += v0.w + v1.w;
                *(float4*)&p_s[lane * KSP + h0 * HS + r0p] = v0;
                *(float4*)&p_s[lane * KSP + (h0 + 1) * HS + r0p] = v1;
            }
#pragma unroll
            for (int rr = 0; rr < 4; rr++)
                avg[(size_t)(i0 + r0p + rr) * Nn + j0 + lane] = sumv[rr] * 0.125f;
        }
        __syncthreads();
        const float* whb = wh_s + b * WB;
#pragma unroll 4
        for (int k = 0; k < TJ; k++) {
            const float* pb = &p_s[k * KSP + hg * HS + r0g];
            ulonglong2 a01 = *(const ulonglong2*)(pb);
            ulonglong2 a23 = *(const ulonglong2*)(pb + 4);
            ulonglong2 a45 = *(const ulonglong2*)(pb + 8);
            ulonglong2 a67 = *(const ulonglong2*)(pb + 12);
            float4 b4 = *(const float4*)&whb[k * CC + col0];
            u64 bd[4];
            asm("mov.b64 %0, {%1, %1};" : "=l"(bd[0]) : "f"(b4.x));
            asm("mov.b64 %0, {%1, %1};" : "=l"(bd[1]) : "f"(b4.y));
            asm("mov.b64 %0, {%1, %1};" : "=l"(bd[2]) : "f"(b4.z));
            asm("mov.b64 %0, {%1, %1};" : "=l"(bd[3]) : "f"(b4.w));
#pragma unroll
            for (int c = 0; c < 4; c++) {
                ffma2(acc[0][c], a01.x, bd[c]);
                ffma2(acc[1][c], a01.y, bd[c]);
                ffma2(acc[2][c], a23.x, bd[c]);
                ffma2(acc[3][c], a23.y, bd[c]);
                ffma2(acc[4][c], a45.x, bd[c]);
                ffma2(acc[5][c], a45.y, bd[c]);
                ffma2(acc[6][c], a67.x, bd[c]);
                ffma2(acc[7][c], a67.y, bd[c]);
            }
        }
        cp_waitall();
        __syncthreads();
    }
    float* dst = g_hp[blockIdx.x];
#pragma unroll
    for (int rp = 0; rp < 8; rp++) {
        float2 c0 = unpk(acc[rp][0]), c1 = unpk(acc[rp][1]);
        float2 c2 = unpk(acc[rp][2]), c3 = unpk(acc[rp][3]);
        int r = i0 + r0g + rp * 2;
        *(float4*)&dst[(size_t)r * CC + col0] = make_float4(c0.x, c1.x, c2.x, c3.x);
        *(float4*)&dst[(size_t)(r + 1) * CC + col0] = make_float4(c0.y, c1.y, c2.y, c3.y);
    }
}

// ====== K4: elu + Wh2 = x2 @ W_out + src2/dst2 (round-10 form) ======
__global__ void __launch_bounds__(128) k4_out(const float* __restrict__ Wout,
                                              const float* __restrict__ aos,
                                              const float* __restrict__ aod) {
    int w = threadIdx.x >> 5, lane = threadIdx.x & 31;
    int row = blockIdx.x * 4 + w;
    const float* h0 = g_hp[0] + (size_t)row * CC;
    const float* h1 = g_hp[1] + (size_t)row * CC;
    const float* h2 = g_hp[2] + (size_t)row * CC;
    float acc[NC];
#pragma unroll
    for (int c = 0; c < NC; c++) acc[c] = 0.f;
#pragma unroll 4
    for (int m = 0; m < FIN / 32; m++) {
        int k = m * 32 + lane;
        float v = h0[k] + h1[k] + h2[k];
        v = v > 0.f ? v : (__expf(v) - 1.f);   // elu
        const float4* wp = (const float4*)(Wout + (size_t)k * NC);
        float4 w0 = wp[0], w1 = wp[1], w2 = wp[2], w3 = wp[3];
        acc[0] += v * w0.x; acc[1] += v * w0.y; acc[2] += v * w0.z; acc[3] += v * w0.w;
        acc[4] += v * w1.x; acc[5] += v * w1.y; acc[6] += v * w1.z; acc[7] += v * w1.w;
        acc[8] += v * w2.x; acc[9] += v * w2.y; acc[10] += v * w2.z; acc[11] += v * w2.w;
        acc[12] += v * w3.x; acc[13] += v * w3.y; acc[14] += v * w3.z; acc[15] += v * w3.w;
    }
#pragma unroll
    for (int c = 0; c < NC; c++) {
        float v = acc[c];
#pragma unroll
        for (int o = 16; o; o >>= 1) v += __shfl_down_sync(0xffffffffu, v, o);
        acc[c] = v;
    }
    if (!lane) {
        float s = 0.f, d = 0.f;
#pragma unroll
        for (int c = 0; c < NC; c++) {
            g_Wh2[(size_t)row * NC + c] = acc[c];
            s += acc[c] * aos[c];
            d += acc[c] * aod[c];
        }
        g_s2[row] = s;
        g_d2[row] = d;
    }
}

// ====== K5: output attention + log_softmax (no p buffer; exp recomputed) ====
__global__ void __launch_bounds__(256) k5_final(const int* __restrict__ adj,
                                                float* __restrict__ out) {
    __shared__ float w2s[256 * 17];
    __shared__ float red[64];
    int i0 = blockIdx.x * TI5;
    int t = threadIdx.x, lane = t & 31, w = t >> 5;

    float zs[TI5], s2v[TI5];
#pragma unroll
    for (int i = 0; i < TI5; i++) { zs[i] = 0.f; s2v[i] = g_s2[i0 + i]; }
    // phase A: Z row sums (identical arithmetic to stored-p version)
    for (int j = t; j < Nn; j += 256) {
        float dv = g_d2[j];
#pragma unroll
        for (int i = 0; i < TI5; i++) {
            if (adj[(size_t)(i0 + i) * Nn + j] > 0)
                zs[i] += __expf(lrelu(s2v[i] + dv));
        }
    }
#pragma unroll
    for (int i = 0; i < TI5; i++) {
        float v = zs[i];
#pragma unroll
        for (int o = 16; o; o >>= 1) v += __shfl_down_sync(0xffffffffu, v, o);
        if (!lane) red[w * TI5 + i] = v;
    }
    __syncthreads();
    float Z = 0.f;
#pragma unroll
    for (int ww = 0; ww < 8; ww++) Z += red[ww * TI5 + w];
    float zinv = 1.f / Z;
    float s2w = s2v[w];
    const int* arow = adj + (size_t)(i0 + w) * Nn;

    // phase B: unnormalized accumulate with recomputed exp (bit-identical)
    float acc[NC];
#pragma unroll
    for (int c = 0; c < NC; c++) acc[c] = 0.f;
    for (int j0 = 0; j0 < Nn; j0 += 256) {
        __syncthreads();
        {
            const float4* gw = (const float4*)&g_Wh2[(size_t)(j0 + t) * NC];
            float4 v0 = gw[0], v1 = gw[1], v2 = gw[2], v3 = gw[3];
            float* ds = &w2s[t * 17];
            ds[0] = v0.x; ds[1] = v0.y; ds[2] = v0.z; ds[3] = v0.w;
            ds[4] = v1.x; ds[5] = v1.y; ds[6] = v1.z; ds[7] = v1.w;
            ds[8] = v2.x; ds[9] = v2.y; ds[10] = v2.z; ds[11] = v2.w;
            ds[12] = v3.x; ds[13] = v3.y; ds[14] = v3.z; ds[15] = v3.w;
        }
        __syncthreads();
#pragma unroll
        for (int jj0 = 0; jj0 < 256; jj0 += 32) {
            int jj = jj0 + lane;
            int j = j0 + jj;
            float pv = 0.f;
            if (arow[j] > 0)
                pv = __expf(lrelu(s2w + g_d2[j]));
            const float* wr = &w2s[jj * 17];
#pragma unroll
            for (int c = 0; c < NC; c++) acc[c] += pv * wr[c];
        }
    }
#pragma unroll
    for (int c = 0; c < NC; c++) {
        float v = acc[c];
#pragma unroll
        for (int o = 16; o; o >>= 1) v += __shfl_down_sync(0xffffffffu, v, o);
        acc[c] = v;
    }
    if (!lane) {
        float ho[NC];
        float mx = -1e30f;
#pragma unroll
        for (int c = 0; c < NC; c++) { ho[c] = acc[c] * zinv; mx = fmaxf(mx, ho[c]); }
        float se = 0.f;
#pragma unroll
        for (int c = 0; c < NC; c++) se += __expf(ho[c] - mx);
        float lse = mx + __logf(se);
#pragma unroll
        for (int c = 0; c < NC; c++) out[(size_t)(i0 + w) * NC + c] = ho[c] - lse;
    }
}

// =======================================================================
extern "C" void kernel_launch(void* const* d_in, const int* in_sizes, int n_in,
                              void* d_out, int out_size) {
    const float* x = (const float*)d_in[0];
    const int* adj = (const int*)d_in[1];
    const float* Whd = (const float*)d_in[2];
    const float* a_src = (const float*)d_in[3];
    const float* a_dst = (const float*)d_in[4];
    const float* Wout = (const float*)d_in[5];
    const float* aos = (const float*)d_in[6];
    const float* aod = (const float*)d_in[7];
    float* out = (float*)d_out;
    float* avg = out + (size_t)Nn * NC;

    const int SMEM3 = 54912 * 4;   // 219,648 B
    cudaFuncSetAttribute(k3_att, cudaFuncAttributeMaxDynamicSharedMemorySize, SMEM3);

    k1_gemm<<<dim3(CC / 64, Nn / 64), 256>>>(x, Whd, a_src, a_dst);
    k2_z<<<Nn, 256>>>(adj);
    k3_att<<<dim3(JSPLIT, Nn / TI), 512, SMEM3>>>(adj, avg);
    k4_out<<<Nn / 4, 128>>>(Wout, aos, aod);
    k5_final<<<Nn / TI5, 256>>>(adj, out);
}

// round 15
// speedup vs baseline: 1.1470x; 1.0130x over previous
#include <cuda_runtime.h>
#include <cstdint>

#define Nn   3072
#define FIN  512
#define NH   8
#define CC   512
#define NC   16
#define LRA  0.2f
#define JSPLIT 3
#define JCHUNK 1024
#define TI   64
#define TJ   32
#define NT3  32      // JCHUNK/TJ
#define KSP  516     // p_s per-j stride in floats (129 float4s -> conflict-free)
#define HS   64
#define WB   16384   // wh_s buffer stride (floats)
#define TI5  8

typedef unsigned long long u64;
typedef uint32_t u32;

// ---- static device scratch ----
__device__ float g_Wh[Nn * CC];
__device__ float g_srcT[Nn * NH], g_dstT[Nn * NH], g_Zinv[Nn * NH];
__device__ float g_hp[JSPLIT][Nn * CC];
__device__ float g_Wh2[Nn * NC];
__device__ float g_s2[Nn], g_d2[Nn];

__device__ __forceinline__ float lrelu(float x) { return fmaxf(x, LRA * x); }
__device__ __forceinline__ void ffma2(u64& d, u64 a, u64 b) {
    asm("fma.rn.f32x2 %0, %1, %2, %0;" : "+l"(d) : "l"(a), "l"(b));
}
__device__ __forceinline__ float2 unpk(u64 v) {
    float2 r;
    asm("mov.b64 {%0, %1}, %2;" : "=f"(r.x), "=f"(r.y) : "l"(v));
    return r;
}
__device__ __forceinline__ void cp16(u32 s, const void* g) {
    asm volatile("cp.async.cg.shared.global [%0], [%1], 16;" :: "r"(s), "l"(g));
}
__device__ __forceinline__ void cp_commit() {
    asm volatile("cp.async.commit_group;" ::: "memory");
}
__device__ __forceinline__ void cp_waitall() {
    asm volatile("cp.async.wait_group 0;" ::: "memory");
}

// ====== K1: Wh = x @ W (f32x2, pipelined) + fused src/dst projections ======
__global__ void __launch_bounds__(256) k1_gemm(const float* __restrict__ x,
                                               const float* __restrict__ W,
                                               const float* __restrict__ a_src,
                                               const float* __restrict__ a_dst) {
    __shared__ float As[16][64], Bs[16][64];
    int t = threadIdx.x, tx = t & 15, ty = t >> 4;
    int row0 = blockIdx.y * 64, col0 = blockIdx.x * 64;
    int h = col0 >> 6;
    const float* Wb = W + (size_t)h * FIN * 64;
    int ra_r = t >> 2, ra_c = (t & 3) << 2, rb_r = t >> 4, rb_c = (t & 15) << 2;
    float4 ra = *(const float4*)&x[(size_t)(row0 + ra_r) * FIN + ra_c];
    float4 rb = *(const float4*)&Wb[(size_t)rb_r * 64 + rb_c];
    u64 acc[2][4];
#pragma unroll
    for (int i = 0; i < 2; i++)
#pragma unroll
        for (int j = 0; j < 4; j++) acc[i][j] = 0ull;
    for (int k0 = 0; k0 < FIN; k0 += 16) {
        As[ra_c][ra_r] = ra.x; As[ra_c + 1][ra_r] = ra.y;
        As[ra_c + 2][ra_r] = ra.z; As[ra_c + 3][ra_r] = ra.w;
        *(float4*)&Bs[rb_r][rb_c] = rb;
        __syncthreads();
        if (k0 + 16 < FIN) {
            ra = *(const float4*)&x[(size_t)(row0 + ra_r) * FIN + k0 + 16 + ra_c];
            rb = *(const float4*)&Wb[(size_t)(k0 + 16 + rb_r) * 64 + rb_c];
        }
#pragma unroll
        for (int k = 0; k < 16; k++) {
            ulonglong2 ap = *(const ulonglong2*)&As[k][ty * 4];
            float4 b4 = *(const float4*)&Bs[k][tx * 4];
            u64 bd[4];
            asm("mov.b64 %0, {%1, %1};" : "=l"(bd[0]) : "f"(b4.x));
            asm("mov.b64 %0, {%1, %1};" : "=l"(bd[1]) : "f"(b4.y));
            asm("mov.b64 %0, {%1, %1};" : "=l"(bd[2]) : "f"(b4.z));
            asm("mov.b64 %0, {%1, %1};" : "=l"(bd[3]) : "f"(b4.w));
#pragma unroll
            for (int c = 0; c < 4; c++) {
                ffma2(acc[0][c], ap.x, bd[c]);
                ffma2(acc[1][c], ap.y, bd[c]);
            }
        }
        __syncthreads();
    }
    float4 as4 = *(const float4*)&a_src[col0 + tx * 4];
    float4 ad4 = *(const float4*)&a_dst[col0 + tx * 4];
    float sr_[4], dr_[4];
#pragma unroll
    for (int rp = 0; rp < 2; rp++) {
        float2 cv[4];
#pragma unroll
        for (int c = 0; c < 4; c++) cv[c] = unpk(acc[rp][c]);
        int r = row0 + ty * 4 + rp * 2;
        *(float4*)&g_Wh[(size_t)r * CC + col0 + tx * 4] =
            make_float4(cv[0].x, cv[1].x, cv[2].x, cv[3].x);
        *(float4*)&g_Wh[(size_t)(r + 1) * CC + col0 + tx * 4] =
            make_float4(cv[0].y, cv[1].y, cv[2].y, cv[3].y);
        sr_[rp * 2]     = cv[0].x * as4.x + cv[1].x * as4.y + cv[2].x * as4.z + cv[3].x * as4.w;
        sr_[rp * 2 + 1] = cv[0].y * as4.x + cv[1].y * as4.y + cv[2].y * as4.z + cv[3].y * as4.w;
        dr_[rp * 2]     = cv[0].x * ad4.x + cv[1].x * ad4.y + cv[2].x * ad4.z + cv[3].x * ad4.w;
        dr_[rp * 2 + 1] = cv[0].y * ad4.x + cv[1].y * ad4.y + cv[2].y * ad4.z + cv[3].y * ad4.w;
    }
#pragma unroll
    for (int rr = 0; rr < 4; rr++) {
        float s = sr_[rr], d = dr_[rr];
#pragma unroll
        for (int o = 8; o; o >>= 1) {
            s += __shfl_down_sync(0xffffffffu, s, o, 16);
            d += __shfl_down_sync(0xffffffffu, d, o, 16);
        }
        if (tx == 0) {
            int r = row0 + ty * 4 + rr;
            g_srcT[r * NH + h] = s;
            g_dstT[r * NH + h] = d;
        }
    }
}

// ========= K2: Z[h,i] — stride-256 unroll x4, unconditional batched loads ===
__global__ void __launch_bounds__(256) k2_z(const int* __restrict__ adj) {
    int i = blockIdx.x;
    float sr[NH], sum[NH];
#pragma unroll
    for (int h = 0; h < NH; h++) { sr[h] = g_srcT[i * NH + h]; sum[h] = 0.f; }
    const int* arow = adj + (size_t)i * Nn;
    int t = threadIdx.x;
#pragma unroll
    for (int it = 0; it < 3; it++) {
        int jb = it * 1024 + t;
        // unconditional batched loads: 4 adj + 8 float4 (coalesced; MLP ~12)
        int a0 = arow[jb];
        int a1 = arow[jb + 256];
        int a2 = arow[jb + 512];
        int a3 = arow[jb + 768];
        const float4* p0 = (const float4*)(g_dstT + (size_t)jb * NH);
        const float4* p1 = (const float4*)(g_dstT + (size_t)(jb + 256) * NH);
        const float4* p2 = (const float4*)(g_dstT + (size_t)(jb + 512) * NH);
        const float4* p3 = (const float4*)(g_dstT + (size_t)(jb + 768) * NH);
        float4 q0a = p0[0], q0b = p0[1];
        float4 q1a = p1[0], q1b = p1[1];
        float4 q2a = p2[0], q2b = p2[1];
        float4 q3a = p3[0], q3b = p3[1];
        if (a0 > 0) {
            float dv[8] = {q0a.x, q0a.y, q0a.z, q0a.w, q0b.x, q0b.y, q0b.z, q0b.w};
#pragma unroll
            for (int h = 0; h < NH; h++) sum[h] += __expf(lrelu(sr[h] + dv[h]));
        }
        if (a1 > 0) {
            float dv[8] = {q1a.x, q1a.y, q1a.z, q1a.w, q1b.x, q1b.y, q1b.z, q1b.w};
#pragma unroll
            for (int h = 0; h < NH; h++) sum[h] += __expf(lrelu(sr[h] + dv[h]));
        }
        if (a2 > 0) {
            float dv[8] = {q2a.x, q2a.y, q2a.z, q2a.w, q2b.x, q2b.y, q2b.z, q2b.w};
#pragma unroll
            for (int h = 0; h < NH; h++) sum[h] += __expf(lrelu(sr[h] + dv[h]));
        }
        if (a3 > 0) {
            float dv[8] = {q3a.x, q3a.y, q3a.z, q3a.w, q3b.x, q3b.y, q3b.z, q3b.w};
#pragma unroll
            for (int h = 0; h < NH; h++) sum[h] += __expf(lrelu(sr[h] + dv[h]));
        }
    }
    __shared__ float red[8][NH];
    int lane = t & 31, w = t >> 5;
#pragma unroll
    for (int h = 0; h < NH; h++) {
        float v = sum[h];
#pragma unroll
        for (int o = 16; o; o >>= 1) v += __shfl_down_sync(0xffffffffu, v, o);
        if (!lane) red[w][h] = v;
    }
    __syncthreads();
    if (t < NH) {
        float v = 0.f;
#pragma unroll
        for (int ww = 0; ww < 8; ww++) v += red[ww][t];
        g_Zinv[i * NH + t] = 1.f / v;
    }
}

// ====== K3: fused pgen + avg write + FFMA2 (att @ Wh) — round-10 form ======
__global__ void __launch_bounds__(512) k3_att(const int* __restrict__ adj,
                                              float* __restrict__ avg) {
    extern __shared__ float sm[];
    float* wh_s   = sm;
    float* p_s    = sm + 32768;
    float* src_s  = sm + 49280;
    float* zinv_s = sm + 49792;
    float* dst_b  = sm + 50304;
    int*   adj_b  = (int*)(sm + 50816);

    int t = threadIdx.x;
    int i0 = blockIdx.y * TI;
    int jbase = blockIdx.x * JCHUNK;

    src_s[(t & 7) * TI + (t >> 3)]  = g_srcT[i0 * NH + t];
    zinv_s[(t & 7) * TI + (t >> 3)] = g_Zinv[i0 * NH + t];

    int tc = t & 127, tr = t >> 7;
    int lane = t & 31, w = t >> 5;
    int r0p = w * 4;
    int r0g = tr * 16;
    int hg = tc >> 4;
    int col0 = tc * 4;

    u32 whs_u  = (u32)__cvta_generic_to_shared(wh_s);
    u32 adjb_u = (u32)__cvta_generic_to_shared(adj_b);
    u32 dstb_u = (u32)__cvta_generic_to_shared(dst_b);
    int cp_row = t >> 3, cp_seg = (t & 7) << 2;

    auto issue_tile = [&](int tile, int buf) {
        int j0t = jbase + tile * TJ;
        cp16(adjb_u + (u32)(buf * 8192 + ((cp_row << 5) + cp_seg) * 4),
             adj + (size_t)(i0 + cp_row) * Nn + j0t + cp_seg);
        if (t < 64)
            cp16(dstb_u + (u32)(buf * 1024 + t * 16),
                 (const char*)g_dstT + ((size_t)j0t * NH + t * 4) * 4);
#pragma unroll
        for (int q = 0; q < 8; q++) {
            int idx = q * 512 + t;
            int jj = idx >> 7, c4 = (idx & 127) << 2;
            cp16(whs_u + (u32)((buf * WB + jj * CC + c4) * 4),
                 &g_Wh[(size_t)(j0t + jj) * CC + c4]);
        }
    };

    issue_tile(0, 0);
    cp_commit();
    cp_waitall();

    u64 acc[8][4];
#pragma unroll
    for (int a = 0; a < 8; a++)
#pragma unroll
        for (int c = 0; c < 4; c++) acc[a][c] = 0ull;
    __syncthreads();

    for (int jt = 0; jt < NT3; jt++) {
        int b = jt & 1;
        int j0 = jbase + jt * TJ;
        if (jt + 1 < NT3) {
            issue_tile(jt + 1, 1 - b);
            cp_commit();
        }
        {
            const float* db = dst_b + b * 256;
            const int*   ab = adj_b + b * 2048;
            float4 dva = *(const float4*)&db[lane * 8];
            float4 dvb = *(const float4*)&db[lane * 8 + 4];
            float dv[8] = {dva.x, dva.y, dva.z, dva.w, dvb.x, dvb.y, dvb.z, dvb.w};
            float msk[4], sumv[4];
#pragma unroll
            for (int rr = 0; rr < 4; rr++) {
                msk[rr] = ab[(r0p + rr) * 32 + lane] > 0 ? 1.f : 0.f;
                sumv[rr] = 0.f;
            }
#pragma unroll
            for (int m = 0; m < 4; m++) {
                int h0 = 2 * m;
                float4 s0 = *(const float4*)&src_s[h0 * TI + r0p];
                float4 s1 = *(const float4*)&src_s[(h0 + 1) * TI + r0p];
                float4 z0 = *(const float4*)&zinv_s[h0 * TI + r0p];
                float4 z1 = *(const float4*)&zinv_s[(h0 + 1) * TI + r0p];
                float4 v0, v1;
                v0.x = __expf(lrelu(s0.x + dv[h0])) * z0.x * msk[0];
                v0.y = __expf(lrelu(s0.y + dv[h0])) * z0.y * msk[1];
                v0.z = __expf(lrelu(s0.z + dv[h0])) * z0.z * msk[2];
                v0.w = __expf(lrelu(s0.w + dv[h0])) * z0.w * msk[3];
                v1.x = __expf(lrelu(s1.x + dv[h0 + 1])) * z1.x * msk[0];
                v1.y = __expf(lrelu(s1.y + dv[h0 + 1])) * z1.y * msk[1];
                v1.z = __expf(lrelu(s1.z + dv[h0 + 1])) * z1.z * msk[2];
                v1.w = __expf(lrelu(s1.w + dv[h0 + 1])) * z1.w * msk[3];
                sumv[0] += v0.x + v1.x; sumv[1] += v0.y + v1.y;
                sumv[2] += v0.z + v1.z; sumv[3] += v0.w + v1.w;
                *(float4*)&p_s[lane * KSP + h0 * HS + r0p] = v0;
                *(float4*)&p_s[lane * KSP + (h0 + 1) * HS + r0p] = v1;
            }
#pragma unroll
            for (int rr = 0; rr < 4; rr++)
                avg[(size_t)(i0 + r0p + rr) * Nn + j0 + lane] = sumv[rr] * 0.125f;
        }
        __syncthreads();
        const float* whb = wh_s + b * WB;
#pragma unroll 4
        for (int k = 0; k < TJ; k++) {
            const float* pb = &p_s[k * KSP + hg * HS + r0g];
            ulonglong2 a01 = *(const ulonglong2*)(pb);
            ulonglong2 a23 = *(const ulonglong2*)(pb + 4);
            ulonglong2 a45 = *(const ulonglong2*)(pb + 8);
            ulonglong2 a67 = *(const ulonglong2*)(pb + 12);
            float4 b4 = *(const float4*)&whb[k * CC + col0];
            u64 bd[4];
            asm("mov.b64 %0, {%1, %1};" : "=l"(bd[0]) : "f"(b4.x));
            asm("mov.b64 %0, {%1, %1};" : "=l"(bd[1]) : "f"(b4.y));
            asm("mov.b64 %0, {%1, %1};" : "=l"(bd[2]) : "f"(b4.z));
            asm("mov.b64 %0, {%1, %1};" : "=l"(bd[3]) : "f"(b4.w));
#pragma unroll
            for (int c = 0; c < 4; c++) {
                ffma2(acc[0][c], a01.x, bd[c]);
                ffma2(acc[1][c], a01.y, bd[c]);
                ffma2(acc[2][c], a23.x, bd[c]);
                ffma2(acc[3][c], a23.y, bd[c]);
                ffma2(acc[4][c], a45.x, bd[c]);
                ffma2(acc[5][c], a45.y, bd[c]);
                ffma2(acc[6][c], a67.x, bd[c]);
                ffma2(acc[7][c], a67.y, bd[c]);
            }
        }
        cp_waitall();
        __syncthreads();
    }
    float* dst = g_hp[blockIdx.x];
#pragma unroll
    for (int rp = 0; rp < 8; rp++) {
        float2 c0 = unpk(acc[rp][0]), c1 = unpk(acc[rp][1]);
        float2 c2 = unpk(acc[rp][2]), c3 = unpk(acc[rp][3]);
        int r = i0 + r0g + rp * 2;
        *(float4*)&dst[(size_t)r * CC + col0] = make_float4(c0.x, c1.x, c2.x, c3.x);
        *(float4*)&dst[(size_t)(r + 1) * CC + col0] = make_float4(c0.y, c1.y, c2.y, c3.y);
    }
}

// ====== K4: elu + Wh2 = x2 @ W_out + src2/dst2 (round-10 form) ======
__global__ void __launch_bounds__(128) k4_out(const float* __restrict__ Wout,
                                              const float* __restrict__ aos,
                                              const float* __restrict__ aod) {
    int w = threadIdx.x >> 5, lane = threadIdx.x & 31;
    int row = blockIdx.x * 4 + w;
    const float* h0 = g_hp[0] + (size_t)row * CC;
    const float* h1 = g_hp[1] + (size_t)row * CC;
    const float* h2 = g_hp[2] + (size_t)row * CC;
    float acc[NC];
#pragma unroll
    for (int c = 0; c < NC; c++) acc[c] = 0.f;
#pragma unroll 4
    for (int m = 0; m < FIN / 32; m++) {
        int k = m * 32 + lane;
        float v = h0[k] + h1[k] + h2[k];
        v = v > 0.f ? v : (__expf(v) - 1.f);   // elu
        const float4* wp = (const float4*)(Wout + (size_t)k * NC);
        float4 w0 = wp[0], w1 = wp[1], w2 = wp[2], w3 = wp[3];
        acc[0] += v * w0.x; acc[1] += v * w0.y; acc[2] += v * w0.z; acc[3] += v * w0.w;
        acc[4] += v * w1.x; acc[5] += v * w1.y; acc[6] += v * w1.z; acc[7] += v * w1.w;
        acc[8] += v * w2.x; acc[9] += v * w2.y; acc[10] += v * w2.z; acc[11] += v * w2.w;
        acc[12] += v * w3.x; acc[13] += v * w3.y; acc[14] += v * w3.z; acc[15] += v * w3.w;
    }
#pragma unroll
    for (int c = 0; c < NC; c++) {
        float v = acc[c];
#pragma unroll
        for (int o = 16; o; o >>= 1) v += __shfl_down_sync(0xffffffffu, v, o);
        acc[c] = v;
    }
    if (!lane) {
        float s = 0.f, d = 0.f;
#pragma unroll
        for (int c = 0; c < NC; c++) {
            g_Wh2[(size_t)row * NC + c] = acc[c];
            s += acc[c] * aos[c];
            d += acc[c] * aod[c];
        }
        g_s2[row] = s;
        g_d2[row] = d;
    }
}

// ====== K5: output attention + log_softmax (no p buffer; exp recomputed) ====
__global__ void __launch_bounds__(256) k5_final(const int* __restrict__ adj,
                                                float* __restrict__ out) {
    __shared__ float w2s[256 * 17];
    __shared__ float red[64];
    int i0 = blockIdx.x * TI5;
    int t = threadIdx.x, lane = t & 31, w = t >> 5;

    float zs[TI5], s2v[TI5];
#pragma unroll
    for (int i = 0; i < TI5; i++) { zs[i] = 0.f; s2v[i] = g_s2[i0 + i]; }
    for (int j = t; j < Nn; j += 256) {
        float dv = g_d2[j];
#pragma unroll
        for (int i = 0; i < TI5; i++) {
            if (adj[(size_t)(i0 + i) * Nn + j] > 0)
                zs[i] += __expf(lrelu(s2v[i] + dv));
        }
    }
#pragma unroll
    for (int i = 0; i < TI5; i++) {
        float v = zs[i];
#pragma unroll
        for (int o = 16; o; o >>= 1) v += __shfl_down_sync(0xffffffffu, v, o);
        if (!lane) red[w * TI5 + i] = v;
    }
    __syncthreads();
    float Z = 0.f;
#pragma unroll
    for (int ww = 0; ww < 8; ww++) Z += red[ww * TI5 + w];
    float zinv = 1.f / Z;
    float s2w = s2v[w];
    const int* arow = adj + (size_t)(i0 + w) * Nn;

    float acc[NC];
#pragma unroll
    for (int c = 0; c < NC; c++) acc[c] = 0.f;
    for (int j0 = 0; j0 < Nn; j0 += 256) {
        __syncthreads();
        {
            const float4* gw = (const float4*)&g_Wh2[(size_t)(j0 + t) * NC];
            float4 v0 = gw[0], v1 = gw[1], v2 = gw[2], v3 = gw[3];
            float* ds = &w2s[t * 17];
            ds[0] = v0.x; ds[1] = v0.y; ds[2] = v0.z; ds[3] = v0.w;
            ds[4] = v1.x; ds[5] = v1.y; ds[6] = v1.z; ds[7] = v1.w;
            ds[8] = v2.x; ds[9] = v2.y; ds[10] = v2.z; ds[11] = v2.w;
            ds[12] = v3.x; ds[13] = v3.y; ds[14] = v3.z; ds[15] = v3.w;
        }
        __syncthreads();
#pragma unroll
        for (int jj0 = 0; jj0 < 256; jj0 += 32) {
            int jj = jj0 + lane;
            int j = j0 + jj;
            float pv = 0.f;
            if (arow[j] > 0)
                pv = __expf(lrelu(s2w + g_d2[j]));
            const float* wr = &w2s[jj * 17];
#pragma unroll
            for (int c = 0; c < NC; c++) acc[c] += pv * wr[c];
        }
    }
#pragma unroll
    for (int c = 0; c < NC; c++) {
        float v = acc[c];
#pragma unroll
        for (int o = 16; o; o >>= 1) v += __shfl_down_sync(0xffffffffu, v, o);
        acc[c] = v;
    }
    if (!lane) {
        float ho[NC];
        float mx = -1e30f;
#pragma unroll
        for (int c = 0; c < NC; c++) { ho[c] = acc[c] * zinv; mx = fmaxf(mx, ho[c]); }
        float se = 0.f;
#pragma unroll
        for (int c = 0; c < NC; c++) se += __expf(ho[c] - mx);
        float lse = mx + __logf(se);
#pragma unroll
        for (int c = 0; c < NC; c++) out[(size_t)(i0 + w) * NC + c] = ho[c] - lse;
    }
}

// =======================================================================
extern "C" void kernel_launch(void* const* d_in, const int* in_sizes, int n_in,
                              void* d_out, int out_size) {
    const float* x = (const float*)d_in[0];
    const int* adj = (const int*)d_in[1];
    const float* Whd = (const float*)d_in[2];
    const float* a_src = (const float*)d_in[3];
    const float* a_dst = (const float*)d_in[4];
    const float* Wout = (const float*)d_in[5];
    const float* aos = (const float*)d_in[6];
    const float* aod = (const float*)d_in[7];
    float* out = (float*)d_out;
    float* avg = out + (size_t)Nn * NC;

    const int SMEM3 = 54912 * 4;   // 219,648 B
    cudaFuncSetAttribute(k3_att, cudaFuncAttributeMaxDynamicSharedMemorySize, SMEM3);

    k1_gemm<<<dim3(CC / 64, Nn / 64), 256>>>(x, Whd, a_src, a_dst);
    k2_z<<<Nn, 256>>>(adj);
    k3_att<<<dim3(JSPLIT, Nn / TI), 512, SMEM3>>>(adj, avg);
    k4_out<<<Nn / 4, 128>>>(Wout, aos, aod);
    k5_final<<<Nn / TI5, 256>>>(adj, out);
}